// round 6
// baseline (speedup 1.0000x reference)
#include <cuda_runtime.h>
#include <cuda_fp16.h>
#include <cstdint>

#define NN    50000
#define EE    250000
#define INF_  9
#define OUTF  84
#define CH    21            // float4 chunks per row (84/4)
#define EPS   1e-5f

#define FIN_BLOCKS  296
#define FIN_THREADS 336
#define FIN_STRIDE  (FIN_BLOCKS * FIN_THREADS)
#define MAX_IT      11

#define PREP_NODES   48                 // nodes per block
#define PREP_G       16                 // node-groups (threads per c)
#define NPT          3                  // nodes per thread
#define PREP_THREADS (CH * PREP_G)      // 336

typedef unsigned long long ull;

// Scratch (static device globals; no runtime allocation)
__device__ __align__(16) uint4 g_uv[NN * CH];     // fp16 {u0..u3, v0..v3} per (node,chunk)
__device__ __align__(16) float g_pre[NN * OUTF];  // x@root + bias, then += scatter-add(msg)
__device__ float g_stats[2 * OUTF];
__device__ float g_scale[OUTF];
__device__ float g_shift[OUTF];
__device__ int   g_count;
__device__ int   g_flag;
__device__ int   g_is64;

// ---- packed f32x2 helpers -------------------------------------------------
__device__ __forceinline__ ull pack2(float a, float b) {
    ull r; asm("mov.b64 %0, {%1, %2};" : "=l"(r) : "f"(a), "f"(b)); return r;
}
__device__ __forceinline__ float2 unpack2(ull v) {
    float2 r; asm("mov.b64 {%0, %1}, %2;" : "=f"(r.x), "=f"(r.y) : "l"(v)); return r;
}
__device__ __forceinline__ ull ffma2(ull a, ull b, ull c) {
    ull d; asm("fma.rn.f32x2 %0, %1, %2, %3;" : "=l"(d) : "l"(a), "l"(b), "l"(c)); return d;
}

// ---------------------------------------------------------------------------
// Kernel A: thread = (chunk c [warp-uniform], node-group g). 3 nodes per
// thread amortize every weight LDS over 18 FFMA2. Outputs staged in shared,
// written out coalesced.
__global__ void __launch_bounds__(PREP_THREADS, 1)
prep_kernel(const float* __restrict__ x,
            const float* __restrict__ nn_w,
            const float* __restrict__ nn_b,
            const float* __restrict__ root,
            const float* __restrict__ bias,
            const int*   __restrict__ ei32) {
    __shared__ float4 swu[INF_ * CH];
    __shared__ float4 swv[INF_ * CH];
    __shared__ float4 swr[INF_ * CH];
    __shared__ float4 sbias[CH];
    __shared__ uint4  s_uv [CH][PREP_NODES + 1];
    __shared__ float4 s_pre[CH][PREP_NODES + 1];

    const int tid = threadIdx.x;

    if (blockIdx.x == 0) {
        if (tid < 2 * OUTF) g_stats[tid] = 0.0f;
        if (tid == 0) {
            g_count = 0;
            g_flag = 0;
            int acc = 0;
            #pragma unroll
            for (int k = 0; k < 64; k++) acc |= ei32[2 * k + 1];  // int64 high dwords == 0
            g_is64 = (acc == 0) ? 1 : 0;
        }
    }

    const float4* w4 = (const float4*)nn_w;
    const float4* b4 = (const float4*)nn_b;
    const float4* r4 = (const float4*)root;
    for (int j = tid; j < INF_ * CH; j += PREP_THREADS) {
        swu[j] = w4[j];
        swv[j] = b4[j];
        swr[j] = r4[j];
    }
    if (tid < CH) sbias[tid] = ((const float4*)bias)[tid];
    __syncthreads();

    const int c  = tid / PREP_G;          // 0..20, warp-uniform across 16-lane halves
    const int g  = tid - c * PREP_G;      // 0..15
    const int n0 = blockIdx.x * PREP_NODES;

    // Load x rows for this thread's 3 nodes (g, g+16, g+32), pre-packed f32x2.
    ull  xp[NPT][INF_];
    bool valid[NPT];
    #pragma unroll
    for (int k = 0; k < NPT; k++) {
        int n = n0 + g + k * PREP_G;
        valid[k] = (n < NN);
        #pragma unroll
        for (int i = 0; i < INF_; i++) {
            float xv = valid[k] ? x[n * INF_ + i] : 0.0f;
            xp[k][i] = pack2(xv, xv);
        }
    }

    float4 bv = sbias[c];
    ull au01[NPT], au23[NPT], av01[NPT], av23[NPT], ap01[NPT], ap23[NPT];
    #pragma unroll
    for (int k = 0; k < NPT; k++) {
        au01[k] = au23[k] = av01[k] = av23[k] = 0ull;
        ap01[k] = pack2(bv.x, bv.y);
        ap23[k] = pack2(bv.z, bv.w);
    }

    const ulonglong2* wu2 = (const ulonglong2*)swu;
    const ulonglong2* wv2 = (const ulonglong2*)swv;
    const ulonglong2* wr2 = (const ulonglong2*)swr;

    #pragma unroll
    for (int i = 0; i < INF_; i++) {
        ulonglong2 wu = wu2[i * CH + c];
        ulonglong2 wv = wv2[i * CH + c];
        ulonglong2 wr = wr2[i * CH + c];
        #pragma unroll
        for (int k = 0; k < NPT; k++) {
            ull xv = xp[k][i];
            au01[k] = ffma2(xv, wu.x, au01[k]); au23[k] = ffma2(xv, wu.y, au23[k]);
            av01[k] = ffma2(xv, wv.x, av01[k]); av23[k] = ffma2(xv, wv.y, av23[k]);
            ap01[k] = ffma2(xv, wr.x, ap01[k]); ap23[k] = ffma2(xv, wr.y, ap23[k]);
        }
    }

    #pragma unroll
    for (int k = 0; k < NPT; k++) {
        if (!valid[k]) continue;
        int nl = g + k * PREP_G;
        float2 u01 = unpack2(au01[k]), u23 = unpack2(au23[k]);
        float2 v01 = unpack2(av01[k]), v23 = unpack2(av23[k]);
        uint4 pk;
        *reinterpret_cast<__half2*>(&pk.x) = __floats2half2_rn(u01.x, u01.y);
        *reinterpret_cast<__half2*>(&pk.y) = __floats2half2_rn(u23.x, u23.y);
        *reinterpret_cast<__half2*>(&pk.z) = __floats2half2_rn(v01.x, v01.y);
        *reinterpret_cast<__half2*>(&pk.w) = __floats2half2_rn(v23.x, v23.y);
        s_uv[c][nl] = pk;
        float2 p01 = unpack2(ap01[k]), p23 = unpack2(ap23[k]);
        s_pre[c][nl] = make_float4(p01.x, p01.y, p23.x, p23.y);
    }
    __syncthreads();

    // Coalesced writeout: linear j = n*CH + c within the block tile.
    const int nb = min(PREP_NODES, NN - n0);
    const int base = n0 * CH;
    uint4*  guv4  = g_uv;
    float4* gpre4 = (float4*)g_pre;
    for (int j = tid; j < nb * CH; j += PREP_THREADS) {
        int nn_ = j / CH;
        int cc  = j - nn_ * CH;
        guv4 [base + j] = s_uv [cc][nn_];
        gpre4[base + j] = s_pre[cc][nn_];
    }
}

// ---------------------------------------------------------------------------
// Kernel B: thread per (edge, chunk). msg4 = a*u4[src] + v4[src]; red.v4 into pre[dst].
__global__ void edge_kernel(const void* __restrict__ ei_raw,
                            const float* __restrict__ ea) {
    int t = blockIdx.x * blockDim.x + threadIdx.x;
    if (t >= EE * CH) return;
    int e = t / CH;
    int c = t - e * CH;

    int src, dst;
    if (g_is64) {
        const long long* ei = (const long long*)ei_raw;
        src = (int)ei[e];
        dst = (int)ei[EE + e];
    } else {
        const int* ei = (const int*)ei_raw;
        src = ei[e];
        dst = ei[EE + e];
    }
    float a = ea[e];

    uint4 pk = g_uv[src * CH + c];
    float2 u01 = __half22float2(*reinterpret_cast<__half2*>(&pk.x));
    float2 u23 = __half22float2(*reinterpret_cast<__half2*>(&pk.y));
    float2 v01 = __half22float2(*reinterpret_cast<__half2*>(&pk.z));
    float2 v23 = __half22float2(*reinterpret_cast<__half2*>(&pk.w));

    float4 m;
    m.x = fmaf(a, u01.x, v01.x);
    m.y = fmaf(a, u01.y, v01.y);
    m.z = fmaf(a, u23.x, v23.x);
    m.w = fmaf(a, u23.y, v23.y);

    float* dptr = g_pre + dst * OUTF + c * 4;
    asm volatile("red.global.add.v4.f32 [%0], {%1, %2, %3, %4};"
                 :: "l"(dptr), "f"(m.x), "f"(m.y), "f"(m.z), "f"(m.w)
                 : "memory");
}

// ---------------------------------------------------------------------------
// Kernel C: fused stats + batchnorm. 296 blocks x 336 threads, all co-resident.
__global__ void __launch_bounds__(FIN_THREADS, 2)
finish_kernel(const float* __restrict__ gamma,
              const float* __restrict__ beta,
              float4* __restrict__ out4) {
    const int tid = threadIdx.x;
    const int c = tid % CH;
    const int col0 = c * 4;
    const float4* pre4 = (const float4*)g_pre;

    float4 vals[MAX_IT];
    float s[4] = {0.f, 0.f, 0.f, 0.f};
    float q[4] = {0.f, 0.f, 0.f, 0.f};
    int cnt = 0;
    for (int i = blockIdx.x * FIN_THREADS + tid; i < NN * CH; i += FIN_STRIDE) {
        float4 w = pre4[i];
        vals[cnt++] = w;
        s[0] += w.x; q[0] = fmaf(w.x, w.x, q[0]);
        s[1] += w.y; q[1] = fmaf(w.y, w.y, q[1]);
        s[2] += w.z; q[2] = fmaf(w.z, w.z, q[2]);
        s[3] += w.w; q[3] = fmaf(w.w, w.w, q[3]);
    }

    __shared__ float sh[8][FIN_THREADS];
    #pragma unroll
    for (int j = 0; j < 4; j++) { sh[j][tid] = s[j]; sh[4 + j][tid] = q[j]; }
    __syncthreads();
    if (tid < CH) {
        #pragma unroll
        for (int j = 0; j < 8; j++) {
            float acc = 0.f;
            #pragma unroll
            for (int r = 0; r < 16; r++) acc += sh[j][tid + r * CH];
            int col = tid * 4 + (j & 3);
            atomicAdd(&g_stats[(j < 4 ? 0 : OUTF) + col], acc);
        }
    }
    __syncthreads();

    __shared__ int sh_last;
    __threadfence();
    if (tid == 0) {
        int prev = atomicAdd(&g_count, 1);
        sh_last = (prev == FIN_BLOCKS - 1) ? 1 : 0;
    }
    __syncthreads();
    if (sh_last) {
        if (tid < OUTF) {
            const float invN = 1.0f / (float)NN;
            float mean = g_stats[tid] * invN;
            float var  = fmaf(-mean, mean, g_stats[OUTF + tid] * invN);
            float sc = rsqrtf(var + EPS) * gamma[tid];
            g_scale[tid] = sc;
            g_shift[tid] = fmaf(-mean, sc, beta[tid]);
        }
        __syncthreads();
        __threadfence();
        if (tid == 0) atomicExch(&g_flag, 1);
    }
    if (tid == 0) {
        volatile int* f = &g_flag;
        while (*f == 0) {}
    }
    __syncthreads();

    float sc[4], sf[4];
    #pragma unroll
    for (int j = 0; j < 4; j++) { sc[j] = g_scale[col0 + j]; sf[j] = g_shift[col0 + j]; }

    int k = 0;
    for (int i = blockIdx.x * FIN_THREADS + tid; i < NN * CH; i += FIN_STRIDE) {
        float4 w = vals[k++];
        w.x = fmaf(w.x, sc[0], sf[0]);
        w.y = fmaf(w.y, sc[1], sf[1]);
        w.z = fmaf(w.z, sc[2], sf[2]);
        w.w = fmaf(w.w, sc[3], sf[3]);
        out4[i] = w;
    }
}

// ---------------------------------------------------------------------------
extern "C" void kernel_launch(void* const* d_in, const int* in_sizes, int n_in,
                              void* d_out, int out_size) {
    const float* x     = (const float*)d_in[0];
    const void*  ei    = d_in[1];
    const float* ea    = (const float*)d_in[2];
    const float* nn_w  = (const float*)d_in[3];
    const float* nn_b  = (const float*)d_in[4];
    const float* root  = (const float*)d_in[5];
    const float* bias  = (const float*)d_in[6];
    const float* gamma = (const float*)d_in[7];
    const float* beta  = (const float*)d_in[8];
    float* out = (float*)d_out;

    {
        int blocks = (NN + PREP_NODES - 1) / PREP_NODES;   // 1042
        prep_kernel<<<blocks, PREP_THREADS>>>(x, nn_w, nn_b, root, bias, (const int*)ei);
    }
    {
        int total = EE * CH;
        edge_kernel<<<(total + 255) / 256, 256>>>(ei, ea);
    }
    finish_kernel<<<FIN_BLOCKS, FIN_THREADS>>>(gamma, beta, (float4*)out);
}